// round 1
// baseline (speedup 1.0000x reference)
#include <cuda_runtime.h>
#include <math.h>

#define NT    4096
#define D     512
#define NHD   16
#define DH    32
#define DEPTH 3
#define DMLP  2048
#define GENES 250
#define GH    64
#define GW    64

// ---------------- scratch (device globals; no allocation allowed) -----------
__device__ float g_x[NT * D];
__device__ float g_xn[NT * D];
__device__ float g_qkv[NT * 3 * D];
__device__ float g_ao[NT * D];
__device__ float g_h[NT * DMLP];
__device__ float g_grid[GH * GW * D];   // [cell][d], D-coalesced
__device__ float g_conv[GH * GW * D];

// ---------------- LayerNorm: one block per row, 128 threads -----------------
__global__ void ln_kernel(const float* __restrict__ in, float* __restrict__ out,
                          const float* __restrict__ gam, const float* __restrict__ bet) {
    int row = blockIdx.x;
    int t   = threadIdx.x;            // 128 threads * float4 = 512
    const float4* xp = (const float4*)(in + (size_t)row * D);
    float4 v = xp[t];
    float s  = v.x + v.y + v.z + v.w;
    float ss = v.x * v.x + v.y * v.y + v.z * v.z + v.w * v.w;
#pragma unroll
    for (int off = 16; off; off >>= 1) {
        s  += __shfl_xor_sync(0xffffffffu, s, off);
        ss += __shfl_xor_sync(0xffffffffu, ss, off);
    }
    __shared__ float sb[4], ssb[4];
    int w = t >> 5, lane = t & 31;
    if (lane == 0) { sb[w] = s; ssb[w] = ss; }
    __syncthreads();
    s  = sb[0] + sb[1] + sb[2] + sb[3];
    ss = ssb[0] + ssb[1] + ssb[2] + ssb[3];
    float mean = s * (1.0f / D);
    float var  = ss * (1.0f / D) - mean * mean;
    float inv  = rsqrtf(var + 1e-5f);
    float4 g4 = ((const float4*)gam)[t];
    float4 b4 = ((const float4*)bet)[t];
    float4 o;
    o.x = (v.x - mean) * inv * g4.x + b4.x;
    o.y = (v.y - mean) * inv * g4.y + b4.y;
    o.z = (v.z - mean) * inv * g4.z + b4.z;
    o.w = (v.w - mean) * inv * g4.w + b4.w;
    ((float4*)(out + (size_t)row * D))[t] = o;
}

// ---------------- GEMM: C[M,OUT] = A[M,K] @ W[OUT,K]^T (+bias, epilogue) ----
// MODE 0: C = v + bias
// MODE 1: C = gelu_exact(v + bias)
// MODE 2: C = res + v + bias
template <int MODE>
__global__ void __launch_bounds__(256) gemm_kernel(
    const float* __restrict__ A, const float* __restrict__ W,
    const float* __restrict__ bias, const float* __restrict__ res,
    float* __restrict__ C, int M, int OUT, int K) {
    __shared__ __align__(16) float As[16][64];
    __shared__ __align__(16) float Bs[16][64];
    int t  = threadIdx.x;
    int tx = t & 15, ty = t >> 4;
    int bx = blockIdx.x, by = blockIdx.y;
    int r  = t >> 2, c4 = t & 3;     // loader mapping: 64 rows x 4 float4
    int arow = by * 64 + r;
    int brow = bx * 64 + r;
    float acc[4][4];
#pragma unroll
    for (int i = 0; i < 4; i++)
#pragma unroll
        for (int j = 0; j < 4; j++) acc[i][j] = 0.f;

    for (int kt = 0; kt < K; kt += 16) {
        float4 a = *(const float4*)(A + (size_t)arow * K + kt + c4 * 4);
        float4 bv = make_float4(0.f, 0.f, 0.f, 0.f);
        if (brow < OUT) bv = *(const float4*)(W + (size_t)brow * K + kt + c4 * 4);
        __syncthreads();
        As[c4 * 4 + 0][r] = a.x;  As[c4 * 4 + 1][r] = a.y;
        As[c4 * 4 + 2][r] = a.z;  As[c4 * 4 + 3][r] = a.w;
        Bs[c4 * 4 + 0][r] = bv.x; Bs[c4 * 4 + 1][r] = bv.y;
        Bs[c4 * 4 + 2][r] = bv.z; Bs[c4 * 4 + 3][r] = bv.w;
        __syncthreads();
#pragma unroll
        for (int k = 0; k < 16; k++) {
            float4 av = *(const float4*)&As[k][ty * 4];
            float4 bw = *(const float4*)&Bs[k][tx * 4];
            acc[0][0] += av.x * bw.x; acc[0][1] += av.x * bw.y; acc[0][2] += av.x * bw.z; acc[0][3] += av.x * bw.w;
            acc[1][0] += av.y * bw.x; acc[1][1] += av.y * bw.y; acc[1][2] += av.y * bw.z; acc[1][3] += av.y * bw.w;
            acc[2][0] += av.z * bw.x; acc[2][1] += av.z * bw.y; acc[2][2] += av.z * bw.z; acc[2][3] += av.z * bw.w;
            acc[3][0] += av.w * bw.x; acc[3][1] += av.w * bw.y; acc[3][2] += av.w * bw.z; acc[3][3] += av.w * bw.w;
        }
    }
#pragma unroll
    for (int i = 0; i < 4; i++) {
        int row = by * 64 + ty * 4 + i;
#pragma unroll
        for (int j = 0; j < 4; j++) {
            int col = bx * 64 + tx * 4 + j;
            if (col < OUT) {
                float v = acc[i][j] + bias[col];
                if (MODE == 1) v = 0.5f * v * (1.0f + erff(v * 0.70710678118654752f));
                if (MODE == 2) v += res[(size_t)row * OUT + col];
                C[(size_t)row * OUT + col] = v;
            }
        }
    }
}

// ---------------- Flash attention: thread = one (head, query) row ----------
__global__ void __launch_bounds__(128) attn_kernel() {
    int h   = blockIdx.x;
    int row = blockIdx.y * 128 + threadIdx.x;
    __shared__ float4 Ks[128][8];
    __shared__ float4 Vs[128][8];
    float4 q[8];
    const float4* qp = (const float4*)(g_qkv + (size_t)row * (3 * D) + h * DH);
#pragma unroll
    for (int dd = 0; dd < 8; dd++) q[dd] = qp[dd];
    float m = -1e30f, l = 0.f;
    float o[32];
#pragma unroll
    for (int d = 0; d < 32; d++) o[d] = 0.f;
    const float scale = 0.17677669529663687f;   // 1/sqrt(32)

    for (int j0 = 0; j0 < NT; j0 += 128) {
#pragma unroll
        for (int i = 0; i < 8; i++) {
            int lin = i * 128 + threadIdx.x;
            int j = lin >> 3, dd = lin & 7;
            const float* base = g_qkv + (size_t)(j0 + j) * (3 * D) + h * DH;
            Ks[j][dd] = ((const float4*)(base + D))[dd];
            Vs[j][dd] = ((const float4*)(base + 2 * D))[dd];
        }
        __syncthreads();
        for (int j = 0; j < 128; j++) {
            float s = 0.f;
#pragma unroll
            for (int dd = 0; dd < 8; dd++) {
                float4 k4 = Ks[j][dd];
                s += q[dd].x * k4.x; s += q[dd].y * k4.y;
                s += q[dd].z * k4.z; s += q[dd].w * k4.w;
            }
            s *= scale;
            if (s > m) {                 // rare: rescale accumulators
                float corr = __expf(m - s);
                l *= corr;
#pragma unroll
                for (int d = 0; d < 32; d++) o[d] *= corr;
                m = s;
            }
            float p = __expf(s - m);
            l += p;
#pragma unroll
            for (int dd = 0; dd < 8; dd++) {
                float4 v4 = Vs[j][dd];
                o[dd * 4 + 0] += p * v4.x; o[dd * 4 + 1] += p * v4.y;
                o[dd * 4 + 2] += p * v4.z; o[dd * 4 + 3] += p * v4.w;
            }
        }
        __syncthreads();
    }
    float inv = 1.f / l;
    float* op = g_ao + (size_t)row * D + h * DH;
#pragma unroll
    for (int d = 0; d < 32; d++) op[d] = o[d] * inv;
}

// ---------------- depthwise conv on 64x64 grid ------------------------------
__global__ void scatter_kernel(const int* __restrict__ coords) {
    int idx = blockIdx.x * blockDim.x + threadIdx.x;   // NT * (D/4)
    int n  = idx >> 7;          // D/4 = 128
    int d4 = idx & 127;
    int rr = coords[2 * n], cc = coords[2 * n + 1];
    ((float4*)g_grid)[(size_t)(rr * GW + cc) * 128 + d4] =
        ((const float4*)g_x)[(size_t)n * 128 + d4];
}

__global__ void conv_kernel(const float* __restrict__ ck) {
    int idx = blockIdx.x * blockDim.x + threadIdx.x;   // GH*GW*D
    int d    = idx & (D - 1);
    int cell = idx >> 9;
    int r = cell >> 6, c = cell & 63;
    float acc = 0.f;
#pragma unroll
    for (int kh = 0; kh < 3; kh++) {
        int rr = r + kh - 1;
        if (rr < 0 || rr >= GH) continue;
#pragma unroll
        for (int kw = 0; kw < 3; kw++) {
            int cc = c + kw - 1;
            if (cc < 0 || cc >= GW) continue;
            acc += ck[d * 9 + kh * 3 + kw] * g_grid[(size_t)(rr * GW + cc) * D + d];
        }
    }
    g_conv[(size_t)cell * D + d] = acc;
}

__global__ void gather_kernel(const int* __restrict__ coords, const float* __restrict__ cb) {
    int idx = blockIdx.x * blockDim.x + threadIdx.x;   // NT*D
    int n = idx >> 9, d = idx & (D - 1);
    int rr = coords[2 * n], cc = coords[2 * n + 1];
    g_x[idx] += g_conv[(size_t)(rr * GW + cc) * D + d] + cb[d];
}

// ---------------- host launch ------------------------------------------------
extern "C" void kernel_launch(void* const* d_in, const int* in_sizes, int n_in,
                              void* d_out, int out_size) {
    const float* gf     = (const float*)d_in[0];
    const int*   coords = (const int*)d_in[1];
    int wi = (n_in >= 22) ? 4 : 2;   // skip grid_h/grid_w scalars if present
    const float* ln1_g = (const float*)d_in[wi + 0];
    const float* ln1_b = (const float*)d_in[wi + 1];
    const float* wqkv  = (const float*)d_in[wi + 2];
    const float* bqkv  = (const float*)d_in[wi + 3];
    const float* wo    = (const float*)d_in[wi + 4];
    const float* bo    = (const float*)d_in[wi + 5];
    const float* ln2_g = (const float*)d_in[wi + 6];
    const float* ln2_b = (const float*)d_in[wi + 7];
    const float* w1    = (const float*)d_in[wi + 8];
    const float* b1    = (const float*)d_in[wi + 9];
    const float* w2    = (const float*)d_in[wi + 10];
    const float* b2    = (const float*)d_in[wi + 11];
    const float* ck    = (const float*)d_in[wi + 12];
    const float* cb    = (const float*)d_in[wi + 13];
    const float* lnf_g = (const float*)d_in[wi + 14];
    const float* lnf_b = (const float*)d_in[wi + 15];
    const float* wp    = (const float*)d_in[wi + 16];
    const float* bp    = (const float*)d_in[wi + 17];

    float* out_x    = (float*)d_out;
    float* out_pred = out_x + (size_t)NT * D;

    static float *px = nullptr, *pxn, *pqkv, *pao, *ph;
    if (!px) {
        cudaGetSymbolAddress((void**)&px,   g_x);
        cudaGetSymbolAddress((void**)&pxn,  g_xn);
        cudaGetSymbolAddress((void**)&pqkv, g_qkv);
        cudaGetSymbolAddress((void**)&pao,  g_ao);
        cudaGetSymbolAddress((void**)&ph,   g_h);
    }

    cudaMemcpyAsync(px, gf, (size_t)NT * D * sizeof(float), cudaMemcpyDeviceToDevice);

    for (int i = 0; i < DEPTH; i++) {
        ln_kernel<<<NT, 128>>>(px, pxn, ln1_g + i * D, ln1_b + i * D);
        gemm_kernel<0><<<dim3(3 * D / 64, NT / 64), 256>>>(
            pxn, wqkv + (size_t)i * 3 * D * D, bqkv + i * 3 * D, nullptr, pqkv, NT, 3 * D, D);
        attn_kernel<<<dim3(NHD, NT / 128), 128>>>();
        gemm_kernel<2><<<dim3(D / 64, NT / 64), 256>>>(
            pao, wo + (size_t)i * D * D, bo + i * D, px, px, NT, D, D);
        ln_kernel<<<NT, 128>>>(px, pxn, ln2_g + i * D, ln2_b + i * D);
        gemm_kernel<1><<<dim3(DMLP / 64, NT / 64), 256>>>(
            pxn, w1 + (size_t)i * DMLP * D, b1 + i * DMLP, nullptr, ph, NT, DMLP, D);
        gemm_kernel<2><<<dim3(D / 64, NT / 64), 256>>>(
            ph, w2 + (size_t)i * D * DMLP, b2 + i * D, px, px, NT, D, DMLP);
        scatter_kernel<<<NT * (D / 4) / 256, 256>>>(coords);
        conv_kernel<<<GH * GW * D / 256, 256>>>(ck + (size_t)i * D * 9);
        gather_kernel<<<NT * D / 256, 256>>>(coords, cb + i * D);
    }
    ln_kernel<<<NT, 128>>>(px, out_x, lnf_g, lnf_b);
    gemm_kernel<0><<<dim3((GENES + 63) / 64, NT / 64), 256>>>(
        out_x, wp, bp, nullptr, out_pred, NT, GENES, D);
}